// round 12
// baseline (speedup 1.0000x reference)
#include <cuda_runtime.h>
#include <math.h>

#define NB 2
#define NN 50000
#define NE 640000
#define FD 128
#define NOUT 16
#define MR (NB*NN)   // 100000 rows
#define SB 49        // scan blocks (49*1024 >= NN)
#define FILLB 2500   // fill blocks (NE/256)

// ---------------- device scratch (allocation-free) ----------------
__device__ __align__(256) float g_dinv[NN];
__device__ __align__(256) float g_deg[NN];
__device__ __align__(256) int   g_cnt[NN];
__device__ __align__(256) int   g_cur[NN];
__device__ __align__(256) int   g_rowptr[NN + 1];
__device__ __align__(256) int   g_bsum[SB];
__device__ __align__(256) int   g_boff[SB];
__device__ __align__(256) int   g_esrc[NE];     // src ids sorted by dst
__device__ __align__(256) float g_enorm[NE];    // norm sorted by dst
__device__ __align__(256) float g_bufA[(size_t)MR*FD];   // xw / xw2
__device__ __align__(256) float g_bufH[(size_t)MR*FD];   // aggregated h (pre-relu)
__device__ __align__(256) float g_stats[512];            // sum/sumsq for 2 layers
__device__ __align__(256) float g_W2p[FD*FD];            // a1 ⊙ W2
__device__ __align__(256) float g_cw2[FD];               // c1 @ W2
__device__ __align__(256) float g_Wcp[FD*NOUT];          // a2 ⊙ Wc
__device__ __align__(256) float g_bcp[NOUT];             // bc + c2 @ Wc

// ---------------- prep: init, degree+histogram ----------------
__global__ void k_init() {
    int i = blockIdx.x*blockDim.x + threadIdx.x;
    if (i < NN) { g_deg[i] = 1.0f; g_cnt[i] = 0; }   // self-loop weight = 1
    if (i < 512) g_stats[i] = 0.0f;
}

__global__ void k_deghist(const int* __restrict__ ei, const float* __restrict__ ewp) {
    int e = blockIdx.x*blockDim.x + threadIdx.x;
    if (e >= NE) return;
    int dst = ei[NE + e];
    atomicAdd(&g_deg[dst], expf(ewp[e]));
    atomicAdd(&g_cnt[dst], 1);
}

// ---------------- parallel 3-phase exclusive scan over g_cnt (+dinv in phase 3) ----------------
__global__ __launch_bounds__(1024) void k_scan1() {
    __shared__ int sh[1024];
    const int t = threadIdx.x;
    const int i = blockIdx.x * 1024 + t;
    int v = (i < NN) ? g_cnt[i] : 0;
    sh[t] = v;
    __syncthreads();
    #pragma unroll
    for (int off = 1; off < 1024; off <<= 1) {
        int x = (t >= off) ? sh[t - off] : 0;
        __syncthreads();
        sh[t] += x;
        __syncthreads();
    }
    if (i < NN) g_rowptr[i] = sh[t] - v;        // local exclusive prefix
    if (t == 1023) g_bsum[blockIdx.x] = sh[1023];
}

__global__ void k_scan2() {
    __shared__ int s[SB];
    int t = threadIdx.x;   // 64 threads
    if (t < SB) s[t] = g_bsum[t];
    __syncthreads();
    if (t == 0) {
        int run = 0;
        for (int i = 0; i < SB; i++) { int v = s[i]; s[i] = run; run += v; }
    }
    __syncthreads();
    if (t < SB) g_boff[t] = s[t];
}

__global__ __launch_bounds__(1024) void k_scan3() {
    const int i = blockIdx.x * 1024 + threadIdx.x;
    if (i < NN) {
        int v = g_rowptr[i] + g_boff[blockIdx.x];
        g_rowptr[i] = v;
        g_cur[i]    = v;
        g_dinv[i]   = rsqrtf(g_deg[i]);   // deg >= 1 always
    }
    if (i == 0) g_rowptr[NN] = NE;
}

// ---------------- tf32 GEMM tile body (R4-proven) ----------------
__device__ __forceinline__ unsigned f2tf(float f) {
    unsigned r;
    asm("cvt.rna.tf32.f32 %0, %1;" : "=r"(r) : "f"(f));
    return r;
}

__device__ __forceinline__ void gemm_tile(unsigned (*As)[12], unsigned (*Bs)[136],
                                          const float* __restrict__ A,
                                          const float* __restrict__ B,
                                          float* __restrict__ C,
                                          const float* __restrict__ biasRow,
                                          int reluA, long rowBase) {
    const int t    = threadIdx.x;
    const int warp = t >> 5;
    const int lane = t & 31;
    const int l4   = lane >> 2;        // 0..7
    const int lm4  = lane & 3;         // 0..3
    const int wr   = warp * 16;        // warp's row base in tile

    float c[16][4];
    #pragma unroll
    for (int nt = 0; nt < 16; nt++) {
        int col = nt*8 + 2*lm4;
        float bv0 = biasRow ? biasRow[col]     : 0.f;
        float bv1 = biasRow ? biasRow[col + 1] : 0.f;
        c[nt][0] = bv0; c[nt][1] = bv1;
        c[nt][2] = bv0; c[nt][3] = bv1;
    }

    const int arow = t >> 1;
    const int ak   = (t & 1) * 4;
    long arg = rowBase + arow; if (arg >= MR) arg = MR - 1;
    const int bk = t >> 5;             // 0..7
    const int bn = (t & 31) * 4;

    for (int kc = 0; kc < 16; kc++) {
        float4 av = *(const float4*)(A + arg*FD + kc*8 + ak);
        if (reluA) {
            av.x = fmaxf(av.x, 0.f); av.y = fmaxf(av.y, 0.f);
            av.z = fmaxf(av.z, 0.f); av.w = fmaxf(av.w, 0.f);
        }
        As[arow][ak+0] = f2tf(av.x); As[arow][ak+1] = f2tf(av.y);
        As[arow][ak+2] = f2tf(av.z); As[arow][ak+3] = f2tf(av.w);
        float4 bvv = *(const float4*)(B + (size_t)(kc*8 + bk)*FD + bn);
        Bs[bk][bn+0] = f2tf(bvv.x); Bs[bk][bn+1] = f2tf(bvv.y);
        Bs[bk][bn+2] = f2tf(bvv.z); Bs[bk][bn+3] = f2tf(bvv.w);
        __syncthreads();

        unsigned a0 = As[wr + l4    ][lm4    ];
        unsigned a1 = As[wr + l4 + 8][lm4    ];
        unsigned a2 = As[wr + l4    ][lm4 + 4];
        unsigned a3 = As[wr + l4 + 8][lm4 + 4];
        #pragma unroll
        for (int nt = 0; nt < 16; nt++) {
            unsigned b0 = Bs[lm4    ][nt*8 + l4];
            unsigned b1 = Bs[lm4 + 4][nt*8 + l4];
            asm volatile(
                "mma.sync.aligned.m16n8k8.row.col.f32.tf32.tf32.f32 "
                "{%0,%1,%2,%3}, {%4,%5,%6,%7}, {%8,%9}, {%0,%1,%2,%3};"
                : "+f"(c[nt][0]), "+f"(c[nt][1]), "+f"(c[nt][2]), "+f"(c[nt][3])
                : "r"(a0), "r"(a1), "r"(a2), "r"(a3), "r"(b0), "r"(b1));
        }
        __syncthreads();
    }

    long crow0 = rowBase + wr + l4;
    long crow1 = crow0 + 8;
    #pragma unroll
    for (int nt = 0; nt < 16; nt++) {
        int col = nt*8 + 2*lm4;
        if (crow0 < MR) *(float2*)(C + crow0*FD + col) = make_float2(c[nt][0], c[nt][1]);
        if (crow1 < MR) *(float2*)(C + crow1*FD + col) = make_float2(c[nt][2], c[nt][3]);
    }
}

// standalone GEMM (layer 2)
__global__ __launch_bounds__(256) void k_gemm(const float* __restrict__ A,
                                              const float* __restrict__ B,
                                              float* __restrict__ C,
                                              const float* __restrict__ biasRow,
                                              int reluA) {
    __shared__ unsigned As[128][12];
    __shared__ unsigned Bs[8][136];
    gemm_tile(As, Bs, A, B, C, biasRow, reluA, (long)blockIdx.x * 128);
}

// merged: CSR fill (blocks 0..FILLB-1) + layer-1 GEMM (remaining blocks)
__global__ __launch_bounds__(256) void k_fill_gemm1(const int* __restrict__ ei,
                                                    const float* __restrict__ ewp,
                                                    const float* __restrict__ x,
                                                    const float* __restrict__ W1,
                                                    float* __restrict__ C) {
    __shared__ unsigned As[128][12];
    __shared__ unsigned Bs[8][136];
    if (blockIdx.x < FILLB) {
        int e = blockIdx.x*256 + threadIdx.x;
        if (e < NE) {
            int src = ei[e], dst = ei[NE + e];
            int p = atomicAdd(&g_cur[dst], 1);
            g_esrc[p]  = src;
            g_enorm[p] = g_dinv[src] * expf(ewp[e]) * g_dinv[dst];
        }
        return;
    }
    gemm_tile(As, Bs, x, W1, C, nullptr, 0, (long)(blockIdx.x - FILLB) * 128);
}

// ---------------- CSR aggregation + fused BN stats (no trailing barrier) ----------------
// H[b,n] = dinv[n]^2*A[b,n] + bias + sum_e norm[e]*A[b,src[e]]  (stored pre-relu)
// stats accumulate relu(H); last-arriving warp flushes the block's partial sums.
__global__ __launch_bounds__(256) void k_agg(const float* __restrict__ A,
                                             float* __restrict__ H,
                                             const float* __restrict__ bias,
                                             int statoff) {
    __shared__ float ss[8][256];   // [warp][0:128 sum | 128:256 sumsq]
    __shared__ int cnt;
    int warp = threadIdx.x >> 5;
    int lane = threadIdx.x & 31;
    if (threadIdx.x == 0) cnt = 0;
    __syncthreads();               // uniform start barrier (before variable work)

    int n = blockIdx.x * 8 + warp;
    int b = blockIdx.y;
    float4 r4 = make_float4(0.f, 0.f, 0.f, 0.f);   // relu'd values for stats

    if (n < NN) {
        const float4* Ab = (const float4*)(A + (size_t)b*NN*FD);
        float d = g_dinv[n];
        float sn = d * d;
        float4 v  = Ab[(size_t)n*32 + lane];
        float4 bv = ((const float4*)bias)[lane];
        float4 acc;
        acc.x = fmaf(sn, v.x, bv.x);
        acc.y = fmaf(sn, v.y, bv.y);
        acc.z = fmaf(sn, v.z, bv.z);
        acc.w = fmaf(sn, v.w, bv.w);

        int j = g_rowptr[n];
        const int e = g_rowptr[n + 1];
        for (; j + 1 < e; j += 2) {
            int sA = g_esrc[j],   sB2 = g_esrc[j+1];
            float nA = g_enorm[j], nB = g_enorm[j+1];
            float4 vA = Ab[(size_t)sA*32 + lane];
            float4 vB = Ab[(size_t)sB2*32 + lane];
            acc.x = fmaf(nA, vA.x, acc.x); acc.y = fmaf(nA, vA.y, acc.y);
            acc.z = fmaf(nA, vA.z, acc.z); acc.w = fmaf(nA, vA.w, acc.w);
            acc.x = fmaf(nB, vB.x, acc.x); acc.y = fmaf(nB, vB.y, acc.y);
            acc.z = fmaf(nB, vB.z, acc.z); acc.w = fmaf(nB, vB.w, acc.w);
        }
        if (j < e) {
            int sA = g_esrc[j];
            float nA = g_enorm[j];
            float4 vA = Ab[(size_t)sA*32 + lane];
            acc.x = fmaf(nA, vA.x, acc.x); acc.y = fmaf(nA, vA.y, acc.y);
            acc.z = fmaf(nA, vA.z, acc.z); acc.w = fmaf(nA, vA.w, acc.w);
        }
        ((float4*)(H + ((size_t)b*NN + n)*FD))[lane] = acc;   // pre-relu (consumers apply relu)
        r4.x = fmaxf(acc.x, 0.f); r4.y = fmaxf(acc.y, 0.f);
        r4.z = fmaxf(acc.z, 0.f); r4.w = fmaxf(acc.w, 0.f);
    }

    // covering per-warp stat rows (zeros if inactive)
    *(float4*)&ss[warp][lane*4]       = r4;
    *(float4*)&ss[warp][128 + lane*4] = make_float4(r4.x*r4.x, r4.y*r4.y,
                                                    r4.z*r4.z, r4.w*r4.w);
    __threadfence_block();
    int old = 0;
    if (lane == 0) old = atomicAdd(&cnt, 1);
    old = __shfl_sync(0xffffffffu, old, 0);
    if (old == 7) {                 // last-arriving warp flushes
        __threadfence_block();
        #pragma unroll
        for (int t = lane; t < 256; t += 32) {
            float s = ss[0][t] + ss[1][t] + ss[2][t] + ss[3][t]
                    + ss[4][t] + ss[5][t] + ss[6][t] + ss[7][t];
            atomicAdd(&g_stats[statoff + t], s);
        }
    }
}

// ---------------- fold BN1 into W2: W2' = a1⊙W2, cw2 = c1@W2 ----------------
__global__ void k_fin1(const float* __restrict__ W2, const float* __restrict__ g1,
                       const float* __restrict__ be1) {
    __shared__ float a[FD], c[FD];
    int t = threadIdx.x;   // 128
    float inv = 1.0f / (float)MR;
    float mu  = g_stats[t] * inv;
    float var = g_stats[128 + t] * inv - mu*mu;
    float av  = g1[t] * rsqrtf(var + 1e-5f);
    a[t] = av; c[t] = be1[t] - mu*av;
    __syncthreads();
    float acc = 0.f;
    for (int f = 0; f < FD; f++) {
        float w = W2[f*FD + t];
        g_W2p[f*FD + t] = a[f]*w;
        acc = fmaf(c[f], w, acc);
    }
    g_cw2[t] = acc;
}

// ---------------- fold BN2 into Wc: Wc' = a2⊙Wc, bc' = bc + c2@Wc ----------------
__global__ void k_fin2(const float* __restrict__ Wc, const float* __restrict__ bc,
                       const float* __restrict__ g2, const float* __restrict__ be2) {
    __shared__ float a[FD], c[FD];
    int t = threadIdx.x;   // 128
    float inv = 1.0f / (float)MR;
    float mu  = g_stats[256 + t] * inv;
    float var = g_stats[384 + t] * inv - mu*mu;
    float av  = g2[t] * rsqrtf(var + 1e-5f);
    a[t] = av; c[t] = be2[t] - mu*av;
    __syncthreads();
    if (t < NOUT) {
        float acc = bc[t];
        for (int f = 0; f < FD; f++) {
            float w = Wc[f*NOUT + t];
            g_Wcp[f*NOUT + t] = a[f]*w;
            acc = fmaf(c[f], w, acc);
        }
        g_bcp[t] = acc;
    }
}

// ---------------- output head: out = relu(H) @ Wc' + bc', float4 loads ----------------
__global__ void k_out(float* __restrict__ out) {
    __shared__ float Ws[FD*NOUT];
    __shared__ float Hs[8][FD];
    int t = threadIdx.x;   // 128
    #pragma unroll
    for (int i = 0; i < 4; i++)
        *(float4*)&Ws[(t + 128*i)*4] = *(const float4*)&g_Wcp[(t + 128*i)*4];
    long rb = (long)blockIdx.x * 8;
    #pragma unroll
    for (int j = 0; j < 2; j++) {
        int idx = t + 128*j;
        int row = idx >> 5, l = idx & 31;
        long r = rb + row;
        float4 v = make_float4(0.f, 0.f, 0.f, 0.f);
        if (r < MR) {
            v = *(const float4*)(g_bufH + r*FD + l*4);
            v.x = fmaxf(v.x, 0.f); v.y = fmaxf(v.y, 0.f);
            v.z = fmaxf(v.z, 0.f); v.w = fmaxf(v.w, 0.f);
        }
        *(float4*)&Hs[row][l*4] = v;
    }
    __syncthreads();
    int rl = t >> 4, c = t & 15;
    float acc = g_bcp[c];
    #pragma unroll 8
    for (int f = 0; f < FD; f++) acc = fmaf(Hs[rl][f], Ws[f*NOUT + c], acc);
    long r = rb + rl;
    if (r < MR) out[r*NOUT + c] = acc;
}

// ---------------- launcher ----------------
extern "C" void kernel_launch(void* const* d_in, const int* in_sizes, int n_in,
                              void* d_out, int out_size) {
    const float* x   = (const float*)d_in[0];
    const int*   ei  = (const int*)  d_in[1];
    const float* ewp = (const float*)d_in[2];
    const float* W1  = (const float*)d_in[3];
    const float* b1  = (const float*)d_in[4];
    const float* W2  = (const float*)d_in[5];
    const float* b2  = (const float*)d_in[6];
    const float* g1  = (const float*)d_in[7];
    const float* be1 = (const float*)d_in[8];
    const float* g2  = (const float*)d_in[9];
    const float* be2 = (const float*)d_in[10];
    const float* Wc  = (const float*)d_in[11];
    const float* bc  = (const float*)d_in[12];
    float* out = (float*)d_out;

    float *bufA, *bufH, *W2p, *cw2;
    cudaGetSymbolAddress((void**)&bufA, g_bufA);
    cudaGetSymbolAddress((void**)&bufH, g_bufH);
    cudaGetSymbolAddress((void**)&W2p,  g_W2p);
    cudaGetSymbolAddress((void**)&cw2,  g_cw2);

    const int gemmBlocks = (MR + 127) / 128;          // 782
    const dim3 aggGrid((NN + 7) / 8, NB);             // 6250 x 2

    // prep chain (dinv folded into scan3)
    k_init<<<(NN + 255)/256, 256>>>();
    k_deghist<<<(NE + 255)/256, 256>>>(ei, ewp);
    k_scan1<<<SB, 1024>>>();
    k_scan2<<<1, 64>>>();
    k_scan3<<<SB, 1024>>>();

    // CSR fill overlapped with layer-1 GEMM (independent work, one launch)
    k_fill_gemm1<<<FILLB + gemmBlocks, 256>>>(ei, ewp, x, W1, bufA);

    // Layer 1: aggregation + fused BN stats
    k_agg<<<aggGrid, 256>>>(bufA, bufH, b1, 0);
    k_fin1<<<1, 128>>>(W2, g1, be1);

    // Layer 2 (ReLU in GEMM A-load; BN1 folded into W2p/cw2)
    k_gemm<<<gemmBlocks, 256>>>(bufH, W2p, bufA, cw2, 1);
    k_agg<<<aggGrid, 256>>>(bufA, bufH, b2, 256);
    k_fin2<<<1, 128>>>(Wc, bc, g2, be2);

    // Head (ReLU in load; BN2 folded into Wcp/bcp)
    k_out<<<(MR + 7)/8, 128>>>(out);
}

// round 13
// speedup vs baseline: 1.3586x; 1.3586x over previous
#include <cuda_runtime.h>
#include <math.h>

#define NB 2
#define NN 50000
#define NE 640000
#define FD 128
#define NOUT 16
#define MR (NB*NN)   // 100000 rows
#define SB 49        // scan blocks (49*1024 >= NN)

// ---------------- device scratch (allocation-free) ----------------
__device__ __align__(256) float g_dinv[NN];
__device__ __align__(256) float g_deg[NN];
__device__ __align__(256) int   g_cnt[NN];
__device__ __align__(256) int   g_cur[NN];
__device__ __align__(256) int   g_rowptr[NN + 1];
__device__ __align__(256) int   g_bsum[SB];
__device__ __align__(256) int   g_boff[SB];
__device__ __align__(256) int   g_esrc[NE];     // src ids sorted by dst
__device__ __align__(256) float g_enorm[NE];    // norm sorted by dst
__device__ __align__(256) float g_bufA[(size_t)MR*FD];   // xw / xw2
__device__ __align__(256) float g_bufH[(size_t)MR*FD];   // aggregated h (pre-relu)
__device__ __align__(256) float g_stats[512];            // sum/sumsq for 2 layers
__device__ __align__(256) float g_W2p[FD*FD];            // a1 ⊙ W2
__device__ __align__(256) float g_cw2[FD];               // c1 @ W2
__device__ __align__(256) float g_Wcp[FD*NOUT];          // a2 ⊙ Wc
__device__ __align__(256) float g_bcp[NOUT];             // bc + c2 @ Wc

// ---------------- prep: init, degree+histogram, dinv ----------------
__global__ void k_init() {
    int i = blockIdx.x*blockDim.x + threadIdx.x;
    if (i < NN) { g_deg[i] = 1.0f; g_cnt[i] = 0; }   // self-loop weight = 1
    if (i < 512) g_stats[i] = 0.0f;
}

__global__ void k_deghist(const int* __restrict__ ei, const float* __restrict__ ewp) {
    int e = blockIdx.x*blockDim.x + threadIdx.x;
    if (e >= NE) return;
    int dst = ei[NE + e];
    atomicAdd(&g_deg[dst], expf(ewp[e]));
    atomicAdd(&g_cnt[dst], 1);
}

__global__ void k_dinv() {
    int i = blockIdx.x*blockDim.x + threadIdx.x;
    if (i < NN) g_dinv[i] = rsqrtf(g_deg[i]);   // deg >= 1 always
}

// ---------------- parallel 3-phase exclusive scan over g_cnt ----------------
__global__ __launch_bounds__(1024) void k_scan1() {
    __shared__ int sh[1024];
    const int t = threadIdx.x;
    const int i = blockIdx.x * 1024 + t;
    int v = (i < NN) ? g_cnt[i] : 0;
    sh[t] = v;
    __syncthreads();
    #pragma unroll
    for (int off = 1; off < 1024; off <<= 1) {
        int x = (t >= off) ? sh[t - off] : 0;
        __syncthreads();
        sh[t] += x;
        __syncthreads();
    }
    if (i < NN) g_rowptr[i] = sh[t] - v;        // local exclusive prefix
    if (t == 1023) g_bsum[blockIdx.x] = sh[1023];
}

__global__ void k_scan2() {
    __shared__ int s[SB];
    int t = threadIdx.x;   // 64 threads
    if (t < SB) s[t] = g_bsum[t];
    __syncthreads();
    if (t == 0) {
        int run = 0;
        for (int i = 0; i < SB; i++) { int v = s[i]; s[i] = run; run += v; }
    }
    __syncthreads();
    if (t < SB) g_boff[t] = s[t];
}

__global__ __launch_bounds__(1024) void k_scan3() {
    const int i = blockIdx.x * 1024 + threadIdx.x;
    if (i < NN) {
        int v = g_rowptr[i] + g_boff[blockIdx.x];
        g_rowptr[i] = v;
        g_cur[i]    = v;
    }
    if (i == 0) g_rowptr[NN] = NE;
}

// ---------------- fill CSR buckets (src + norm, sorted by dst) ----------------
__global__ void k_fill(const int* __restrict__ ei, const float* __restrict__ ewp) {
    int e = blockIdx.x*blockDim.x + threadIdx.x;
    if (e >= NE) return;
    int src = ei[e], dst = ei[NE + e];
    int p = atomicAdd(&g_cur[dst], 1);
    g_esrc[p]  = src;
    g_enorm[p] = g_dinv[src] * expf(ewp[e]) * g_dinv[dst];
}

// ---------------- tf32 tensor-core GEMM, double-buffered + prefetch ----------------
// C[MR,128] = reluA?(A)[MR,128] @ B[128,128] (+ biasRow)
__device__ __forceinline__ unsigned f2tf(float f) {
    unsigned r;
    asm("cvt.rna.tf32.f32 %0, %1;" : "=r"(r) : "f"(f));
    return r;
}

__global__ __launch_bounds__(256) void k_gemm(const float* __restrict__ A,
                                              const float* __restrict__ B,
                                              float* __restrict__ C,
                                              const float* __restrict__ biasRow,
                                              int reluA) {
    __shared__ unsigned As[2][128][12];   // ping-pong [m][k], stride 12
    __shared__ unsigned Bs[2][8][136];    // ping-pong [k][n], stride 136
    const int t    = threadIdx.x;
    const int warp = t >> 5;
    const int lane = t & 31;
    const int l4   = lane >> 2;        // 0..7
    const int lm4  = lane & 3;         // 0..3
    const int wr   = warp * 16;        // warp's row base in tile
    const long rowBase = (long)blockIdx.x * 128;

    float c[16][4];
    #pragma unroll
    for (int nt = 0; nt < 16; nt++) {
        int col = nt*8 + 2*lm4;
        float bv0 = biasRow ? biasRow[col]     : 0.f;
        float bv1 = biasRow ? biasRow[col + 1] : 0.f;
        c[nt][0] = bv0; c[nt][1] = bv1;
        c[nt][2] = bv0; c[nt][3] = bv1;
    }

    const int arow = t >> 1;
    const int ak   = (t & 1) * 4;
    long arg = rowBase + arow; if (arg >= MR) arg = MR - 1;
    const int bk = t >> 5;             // 0..7
    const int bn = (t & 31) * 4;

    // load + stage chunk 0 into buffer 0
    float4 av = *(const float4*)(A + arg*FD + ak);
    if (reluA) {
        av.x = fmaxf(av.x, 0.f); av.y = fmaxf(av.y, 0.f);
        av.z = fmaxf(av.z, 0.f); av.w = fmaxf(av.w, 0.f);
    }
    float4 bvv = *(const float4*)(B + (size_t)bk*FD + bn);
    As[0][arow][ak+0] = f2tf(av.x); As[0][arow][ak+1] = f2tf(av.y);
    As[0][arow][ak+2] = f2tf(av.z); As[0][arow][ak+3] = f2tf(av.w);
    Bs[0][bk][bn+0] = f2tf(bvv.x); Bs[0][bk][bn+1] = f2tf(bvv.y);
    Bs[0][bk][bn+2] = f2tf(bvv.z); Bs[0][bk][bn+3] = f2tf(bvv.w);
    __syncthreads();

    int p = 0;
    for (int kc = 0; kc < 16; kc++) {
        // prefetch next chunk into registers (overlaps with MMA below)
        if (kc + 1 < 16) {
            av  = *(const float4*)(A + arg*FD + (kc+1)*8 + ak);
            bvv = *(const float4*)(B + (size_t)((kc+1)*8 + bk)*FD + bn);
            if (reluA) {
                av.x = fmaxf(av.x, 0.f); av.y = fmaxf(av.y, 0.f);
                av.z = fmaxf(av.z, 0.f); av.w = fmaxf(av.w, 0.f);
            }
        }

        unsigned a0 = As[p][wr + l4    ][lm4    ];
        unsigned a1 = As[p][wr + l4 + 8][lm4    ];
        unsigned a2 = As[p][wr + l4    ][lm4 + 4];
        unsigned a3 = As[p][wr + l4 + 8][lm4 + 4];
        #pragma unroll
        for (int nt = 0; nt < 16; nt++) {
            unsigned b0 = Bs[p][lm4    ][nt*8 + l4];
            unsigned b1 = Bs[p][lm4 + 4][nt*8 + l4];
            asm volatile(
                "mma.sync.aligned.m16n8k8.row.col.f32.tf32.tf32.f32 "
                "{%0,%1,%2,%3}, {%4,%5,%6,%7}, {%8,%9}, {%0,%1,%2,%3};"
                : "+f"(c[nt][0]), "+f"(c[nt][1]), "+f"(c[nt][2]), "+f"(c[nt][3])
                : "r"(a0), "r"(a1), "r"(a2), "r"(a3), "r"(b0), "r"(b1));
        }

        // stage next chunk into the other buffer
        if (kc + 1 < 16) {
            int q = p ^ 1;
            As[q][arow][ak+0] = f2tf(av.x); As[q][arow][ak+1] = f2tf(av.y);
            As[q][arow][ak+2] = f2tf(av.z); As[q][arow][ak+3] = f2tf(av.w);
            Bs[q][bk][bn+0] = f2tf(bvv.x); Bs[q][bk][bn+1] = f2tf(bvv.y);
            Bs[q][bk][bn+2] = f2tf(bvv.z); Bs[q][bk][bn+3] = f2tf(bvv.w);
            __syncthreads();   // one barrier per kc
            p = q;
        }
    }

    long crow0 = rowBase + wr + l4;
    long crow1 = crow0 + 8;
    #pragma unroll
    for (int nt = 0; nt < 16; nt++) {
        int col = nt*8 + 2*lm4;
        if (crow0 < MR) *(float2*)(C + crow0*FD + col) = make_float2(c[nt][0], c[nt][1]);
        if (crow1 < MR) *(float2*)(C + crow1*FD + col) = make_float2(c[nt][2], c[nt][3]);
    }
}

// ---------------- CSR aggregation: one warp per node, barrier-free (R4-proven, DO NOT TOUCH) ----------------
// H[b,n] = dinv[n]^2 * A[b,n] + bias + sum_{edges e: dst=n} norm[e] * A[b,src[e]]
__global__ __launch_bounds__(256) void k_agg(const float* __restrict__ A,
                                             float* __restrict__ H,
                                             const float* __restrict__ bias) {
    int warp = threadIdx.x >> 5;
    int lane = threadIdx.x & 31;
    int n = blockIdx.x * 8 + warp;
    if (n >= NN) return;
    int b = blockIdx.y;
    const float4* Ab = (const float4*)(A + (size_t)b*NN*FD);

    float d = g_dinv[n];
    float sn = d * d;
    float4 v  = Ab[(size_t)n*32 + lane];
    float4 bv = ((const float4*)bias)[lane];
    float4 acc;
    acc.x = fmaf(sn, v.x, bv.x);
    acc.y = fmaf(sn, v.y, bv.y);
    acc.z = fmaf(sn, v.z, bv.z);
    acc.w = fmaf(sn, v.w, bv.w);

    int j = g_rowptr[n];
    const int e = g_rowptr[n + 1];
    for (; j + 1 < e; j += 2) {
        int sA = g_esrc[j],   sB2 = g_esrc[j+1];
        float nA = g_enorm[j], nB = g_enorm[j+1];
        float4 vA = Ab[(size_t)sA*32 + lane];
        float4 vB = Ab[(size_t)sB2*32 + lane];
        acc.x = fmaf(nA, vA.x, acc.x); acc.y = fmaf(nA, vA.y, acc.y);
        acc.z = fmaf(nA, vA.z, acc.z); acc.w = fmaf(nA, vA.w, acc.w);
        acc.x = fmaf(nB, vB.x, acc.x); acc.y = fmaf(nB, vB.y, acc.y);
        acc.z = fmaf(nB, vB.z, acc.z); acc.w = fmaf(nB, vB.w, acc.w);
    }
    if (j < e) {
        int sA = g_esrc[j];
        float nA = g_enorm[j];
        float4 vA = Ab[(size_t)sA*32 + lane];
        acc.x = fmaf(nA, vA.x, acc.x); acc.y = fmaf(nA, vA.y, acc.y);
        acc.z = fmaf(nA, vA.z, acc.z); acc.w = fmaf(nA, vA.w, acc.w);
    }
    ((float4*)(H + ((size_t)b*NN + n)*FD))[lane] = acc;
}

// ---------------- per-feature sum/sumsq of relu(H), float4 loads ----------------
__global__ __launch_bounds__(256) void k_relustats(int statoff) {
    __shared__ float ss[8][256];   // [warp][0:128 sum | 128:256 sumsq]
    const int warp = threadIdx.x >> 5;
    const int lane = threadIdx.x & 31;
    const long rb = (long)blockIdx.x * 64;

    float4 s  = make_float4(0.f, 0.f, 0.f, 0.f);
    float4 s2 = make_float4(0.f, 0.f, 0.f, 0.f);
    #pragma unroll
    for (int i = 0; i < 8; i++) {
        long r = rb + warp + 8*i;
        if (r < MR) {
            float4 v = *(const float4*)(g_bufH + r*FD + lane*4);
            v.x = fmaxf(v.x, 0.f); v.y = fmaxf(v.y, 0.f);
            v.z = fmaxf(v.z, 0.f); v.w = fmaxf(v.w, 0.f);
            s.x += v.x; s.y += v.y; s.z += v.z; s.w += v.w;
            s2.x += v.x*v.x; s2.y += v.y*v.y; s2.z += v.z*v.z; s2.w += v.w*v.w;
        }
    }
    *(float4*)&ss[warp][lane*4]       = s;
    *(float4*)&ss[warp][128 + lane*4] = s2;
    __syncthreads();   // uniform work per warp -> no straggler penalty
    int t = threadIdx.x;
    float r = ss[0][t] + ss[1][t] + ss[2][t] + ss[3][t]
            + ss[4][t] + ss[5][t] + ss[6][t] + ss[7][t];
    atomicAdd(&g_stats[statoff + t], r);
}

// ---------------- fold BN1 into W2: W2' = a1⊙W2, cw2 = c1@W2 ----------------
__global__ void k_fin1(const float* __restrict__ W2, const float* __restrict__ g1,
                       const float* __restrict__ be1) {
    __shared__ float a[FD], c[FD];
    int t = threadIdx.x;   // 128
    float inv = 1.0f / (float)MR;
    float mu  = g_stats[t] * inv;
    float var = g_stats[128 + t] * inv - mu*mu;
    float av  = g1[t] * rsqrtf(var + 1e-5f);
    a[t] = av; c[t] = be1[t] - mu*av;
    __syncthreads();
    float acc = 0.f;
    for (int f = 0; f < FD; f++) {
        float w = W2[f*FD + t];
        g_W2p[f*FD + t] = a[f]*w;
        acc = fmaf(c[f], w, acc);
    }
    g_cw2[t] = acc;
}

// ---------------- fold BN2 into Wc: Wc' = a2⊙Wc, bc' = bc + c2@Wc ----------------
__global__ void k_fin2(const float* __restrict__ Wc, const float* __restrict__ bc,
                       const float* __restrict__ g2, const float* __restrict__ be2) {
    __shared__ float a[FD], c[FD];
    int t = threadIdx.x;   // 128
    float inv = 1.0f / (float)MR;
    float mu  = g_stats[256 + t] * inv;
    float var = g_stats[384 + t] * inv - mu*mu;
    float av  = g2[t] * rsqrtf(var + 1e-5f);
    a[t] = av; c[t] = be2[t] - mu*av;
    __syncthreads();
    if (t < NOUT) {
        float acc = bc[t];
        for (int f = 0; f < FD; f++) {
            float w = Wc[f*NOUT + t];
            g_Wcp[f*NOUT + t] = a[f]*w;
            acc = fmaf(c[f], w, acc);
        }
        g_bcp[t] = acc;
    }
}

// ---------------- output head: out = relu(H) @ Wc' + bc', float4 loads ----------------
__global__ void k_out(float* __restrict__ out) {
    __shared__ float Ws[FD*NOUT];
    __shared__ float Hs[8][FD];
    int t = threadIdx.x;   // 128
    #pragma unroll
    for (int i = 0; i < 4; i++)
        *(float4*)&Ws[(t + 128*i)*4] = *(const float4*)&g_Wcp[(t + 128*i)*4];
    long rb = (long)blockIdx.x * 8;
    #pragma unroll
    for (int j = 0; j < 2; j++) {
        int idx = t + 128*j;
        int row = idx >> 5, l = idx & 31;
        long r = rb + row;
        float4 v = make_float4(0.f, 0.f, 0.f, 0.f);
        if (r < MR) {
            v = *(const float4*)(g_bufH + r*FD + l*4);
            v.x = fmaxf(v.x, 0.f); v.y = fmaxf(v.y, 0.f);
            v.z = fmaxf(v.z, 0.f); v.w = fmaxf(v.w, 0.f);
        }
        *(float4*)&Hs[row][l*4] = v;
    }
    __syncthreads();
    int rl = t >> 4, c = t & 15;
    float acc = g_bcp[c];
    #pragma unroll 8
    for (int f = 0; f < FD; f++) acc = fmaf(Hs[rl][f], Ws[f*NOUT + c], acc);
    long r = rb + rl;
    if (r < MR) out[r*NOUT + c] = acc;
}

// ---------------- launcher ----------------
extern "C" void kernel_launch(void* const* d_in, const int* in_sizes, int n_in,
                              void* d_out, int out_size) {
    const float* x   = (const float*)d_in[0];
    const int*   ei  = (const int*)  d_in[1];
    const float* ewp = (const float*)d_in[2];
    const float* W1  = (const float*)d_in[3];
    const float* b1  = (const float*)d_in[4];
    const float* W2  = (const float*)d_in[5];
    const float* b2  = (const float*)d_in[6];
    const float* g1  = (const float*)d_in[7];
    const float* be1 = (const float*)d_in[8];
    const float* g2  = (const float*)d_in[9];
    const float* be2 = (const float*)d_in[10];
    const float* Wc  = (const float*)d_in[11];
    const float* bc  = (const float*)d_in[12];
    float* out = (float*)d_out;

    float *bufA, *bufH, *W2p, *cw2;
    cudaGetSymbolAddress((void**)&bufA, g_bufA);
    cudaGetSymbolAddress((void**)&bufH, g_bufH);
    cudaGetSymbolAddress((void**)&W2p,  g_W2p);
    cudaGetSymbolAddress((void**)&cw2,  g_cw2);

    const int gemmBlocks = (MR + 127) / 128;          // 782
    const dim3 aggGrid((NN + 7) / 8, NB);             // 6250 x 2

    // prep + CSR build (shared by both layers/batches)
    k_init<<<(NN + 255)/256, 256>>>();
    k_deghist<<<(NE + 255)/256, 256>>>(ei, ewp);
    k_dinv<<<(NN + 255)/256, 256>>>();
    k_scan1<<<SB, 1024>>>();
    k_scan2<<<1, 64>>>();
    k_scan3<<<SB, 1024>>>();
    k_fill<<<(NE + 255)/256, 256>>>(ei, ewp);

    // Layer 1
    k_gemm<<<gemmBlocks, 256>>>(x, W1, bufA, nullptr, 0);
    k_agg<<<aggGrid, 256>>>(bufA, bufH, b1);
    k_relustats<<<(MR + 63)/64, 256>>>(0);
    k_fin1<<<1, 128>>>(W2, g1, be1);

    // Layer 2 (ReLU in GEMM A-load; BN1 folded into W2p/cw2)
    k_gemm<<<gemmBlocks, 256>>>(bufH, W2p, bufA, cw2, 1);
    k_agg<<<aggGrid, 256>>>(bufA, bufH, b2);
    k_relustats<<<(MR + 63)/64, 256>>>(256);
    k_fin2<<<1, 128>>>(Wc, bc, g2, be2);

    // Head (ReLU in load; BN2 folded into Wcp/bcp)
    k_out<<<(MR + 7)/8, 128>>>(out);
}

// round 14
// speedup vs baseline: 1.4547x; 1.0707x over previous
#include <cuda_runtime.h>
#include <math.h>

#define NB 2
#define NN 50000
#define NE 640000
#define FD 128
#define NOUT 16
#define MR (NB*NN)   // 100000 rows
#define SB 49        // scan blocks (49*1024 >= NN)

// ---------------- device scratch (allocation-free) ----------------
__device__ __align__(256) float g_dinv[NN];
__device__ __align__(256) float g_deg[NN];
__device__ __align__(256) int   g_cnt[NN];
__device__ __align__(256) int   g_cur[NN];
__device__ __align__(256) int   g_rowptr[NN + 1];
__device__ __align__(256) int   g_bsum[SB];
__device__ __align__(256) int   g_boff[SB];
__device__ __align__(256) int   g_esrc[NE];     // src ids sorted by dst
__device__ __align__(256) float g_enorm[NE];    // norm sorted by dst
__device__ __align__(256) float g_bufA[(size_t)MR*FD];   // xw / xw2
__device__ __align__(256) float g_bufH[(size_t)MR*FD];   // aggregated h (pre-relu)
__device__ __align__(256) float g_stats[512];            // sum/sumsq for 2 layers
__device__ __align__(256) float g_W2p[FD*FD];            // a1 ⊙ W2
__device__ __align__(256) float g_cw2[FD];               // c1 @ W2
__device__ __align__(256) float g_Wcp[FD*NOUT];          // a2 ⊙ Wc
__device__ __align__(256) float g_bcp[NOUT];             // bc + c2 @ Wc

// ---------------- prep: init, degree+histogram ----------------
__global__ void k_init() {
    int i = blockIdx.x*blockDim.x + threadIdx.x;
    if (i < NN) { g_deg[i] = 1.0f; g_cnt[i] = 0; }   // self-loop weight = 1
    if (i < 512) g_stats[i] = 0.0f;
}

__global__ void k_deghist(const int* __restrict__ ei, const float* __restrict__ ewp) {
    int e = blockIdx.x*blockDim.x + threadIdx.x;
    if (e >= NE) return;
    int dst = ei[NE + e];
    atomicAdd(&g_deg[dst], expf(ewp[e]));
    atomicAdd(&g_cnt[dst], 1);
}

// ---------------- parallel 3-phase exclusive scan over g_cnt (+dinv in phase 3) ----------------
__global__ __launch_bounds__(1024) void k_scan1() {
    __shared__ int sh[1024];
    const int t = threadIdx.x;
    const int i = blockIdx.x * 1024 + t;
    int v = (i < NN) ? g_cnt[i] : 0;
    sh[t] = v;
    __syncthreads();
    #pragma unroll
    for (int off = 1; off < 1024; off <<= 1) {
        int x = (t >= off) ? sh[t - off] : 0;
        __syncthreads();
        sh[t] += x;
        __syncthreads();
    }
    if (i < NN) g_rowptr[i] = sh[t] - v;        // local exclusive prefix
    if (t == 1023) g_bsum[blockIdx.x] = sh[1023];
}

__global__ void k_scan2() {
    __shared__ int s[SB];
    int t = threadIdx.x;   // 64 threads
    if (t < SB) s[t] = g_bsum[t];
    __syncthreads();
    if (t == 0) {
        int run = 0;
        for (int i = 0; i < SB; i++) { int v = s[i]; s[i] = run; run += v; }
    }
    __syncthreads();
    if (t < SB) g_boff[t] = s[t];
}

__global__ __launch_bounds__(1024) void k_scan3() {
    const int i = blockIdx.x * 1024 + threadIdx.x;
    if (i < NN) {
        int v = g_rowptr[i] + g_boff[blockIdx.x];
        g_rowptr[i] = v;
        g_cur[i]    = v;
        g_dinv[i]   = rsqrtf(g_deg[i]);   // deg >= 1 always
    }
    if (i == 0) g_rowptr[NN] = NE;
}

// ---------------- fill CSR buckets (src + norm, sorted by dst) ----------------
__global__ void k_fill(const int* __restrict__ ei, const float* __restrict__ ewp) {
    int e = blockIdx.x*blockDim.x + threadIdx.x;
    if (e >= NE) return;
    int src = ei[e], dst = ei[NE + e];
    int p = atomicAdd(&g_cur[dst], 1);
    g_esrc[p]  = src;
    g_enorm[p] = g_dinv[src] * expf(ewp[e]) * g_dinv[dst];
}

// ---------------- tf32 tensor-core GEMM (R4-proven, single buffer) ----------------
// C[MR,128] = reluA?(A)[MR,128] @ B[128,128] (+ biasRow)
__device__ __forceinline__ unsigned f2tf(float f) {
    unsigned r;
    asm("cvt.rna.tf32.f32 %0, %1;" : "=r"(r) : "f"(f));
    return r;
}

__global__ __launch_bounds__(256) void k_gemm(const float* __restrict__ A,
                                              const float* __restrict__ B,
                                              float* __restrict__ C,
                                              const float* __restrict__ biasRow,
                                              int reluA) {
    __shared__ unsigned As[128][12];   // [m][k], stride 12 -> conflict-free frags
    __shared__ unsigned Bs[8][136];    // [k][n], stride 136 -> conflict-free frags
    const int t    = threadIdx.x;
    const int warp = t >> 5;
    const int lane = t & 31;
    const int l4   = lane >> 2;        // 0..7
    const int lm4  = lane & 3;         // 0..3
    const int wr   = warp * 16;        // warp's row base in tile
    const long rowBase = (long)blockIdx.x * 128;

    float c[16][4];
    #pragma unroll
    for (int nt = 0; nt < 16; nt++) {
        int col = nt*8 + 2*lm4;
        float bv0 = biasRow ? biasRow[col]     : 0.f;
        float bv1 = biasRow ? biasRow[col + 1] : 0.f;
        c[nt][0] = bv0; c[nt][1] = bv1;
        c[nt][2] = bv0; c[nt][3] = bv1;
    }

    const int arow = t >> 1;
    const int ak   = (t & 1) * 4;
    long arg = rowBase + arow; if (arg >= MR) arg = MR - 1;
    const int bk = t >> 5;             // 0..7
    const int bn = (t & 31) * 4;

    for (int kc = 0; kc < 16; kc++) {
        float4 av = *(const float4*)(A + arg*FD + kc*8 + ak);
        if (reluA) {
            av.x = fmaxf(av.x, 0.f); av.y = fmaxf(av.y, 0.f);
            av.z = fmaxf(av.z, 0.f); av.w = fmaxf(av.w, 0.f);
        }
        As[arow][ak+0] = f2tf(av.x); As[arow][ak+1] = f2tf(av.y);
        As[arow][ak+2] = f2tf(av.z); As[arow][ak+3] = f2tf(av.w);
        float4 bvv = *(const float4*)(B + (size_t)(kc*8 + bk)*FD + bn);
        Bs[bk][bn+0] = f2tf(bvv.x); Bs[bk][bn+1] = f2tf(bvv.y);
        Bs[bk][bn+2] = f2tf(bvv.z); Bs[bk][bn+3] = f2tf(bvv.w);
        __syncthreads();

        unsigned a0 = As[wr + l4    ][lm4    ];
        unsigned a1 = As[wr + l4 + 8][lm4    ];
        unsigned a2 = As[wr + l4    ][lm4 + 4];
        unsigned a3 = As[wr + l4 + 8][lm4 + 4];
        #pragma unroll
        for (int nt = 0; nt < 16; nt++) {
            unsigned b0 = Bs[lm4    ][nt*8 + l4];
            unsigned b1 = Bs[lm4 + 4][nt*8 + l4];
            asm volatile(
                "mma.sync.aligned.m16n8k8.row.col.f32.tf32.tf32.f32 "
                "{%0,%1,%2,%3}, {%4,%5,%6,%7}, {%8,%9}, {%0,%1,%2,%3};"
                : "+f"(c[nt][0]), "+f"(c[nt][1]), "+f"(c[nt][2]), "+f"(c[nt][3])
                : "r"(a0), "r"(a1), "r"(a2), "r"(a3), "r"(b0), "r"(b1));
        }
        __syncthreads();
    }

    long crow0 = rowBase + wr + l4;
    long crow1 = crow0 + 8;
    #pragma unroll
    for (int nt = 0; nt < 16; nt++) {
        int col = nt*8 + 2*lm4;
        if (crow0 < MR) *(float2*)(C + crow0*FD + col) = make_float2(c[nt][0], c[nt][1]);
        if (crow1 < MR) *(float2*)(C + crow1*FD + col) = make_float2(c[nt][2], c[nt][3]);
    }
}

// ---------------- CSR aggregation: one warp per node, barrier-free (DO NOT TOUCH) ----------------
// H[b,n] = dinv[n]^2 * A[b,n] + bias + sum_{edges e: dst=n} norm[e] * A[b,src[e]]
__global__ __launch_bounds__(256) void k_agg(const float* __restrict__ A,
                                             float* __restrict__ H,
                                             const float* __restrict__ bias) {
    int warp = threadIdx.x >> 5;
    int lane = threadIdx.x & 31;
    int n = blockIdx.x * 8 + warp;
    if (n >= NN) return;
    int b = blockIdx.y;
    const float4* Ab = (const float4*)(A + (size_t)b*NN*FD);

    float d = g_dinv[n];
    float sn = d * d;
    float4 v  = Ab[(size_t)n*32 + lane];
    float4 bv = ((const float4*)bias)[lane];
    float4 acc;
    acc.x = fmaf(sn, v.x, bv.x);
    acc.y = fmaf(sn, v.y, bv.y);
    acc.z = fmaf(sn, v.z, bv.z);
    acc.w = fmaf(sn, v.w, bv.w);

    int j = g_rowptr[n];
    const int e = g_rowptr[n + 1];
    for (; j + 1 < e; j += 2) {
        int sA = g_esrc[j],   sB2 = g_esrc[j+1];
        float nA = g_enorm[j], nB = g_enorm[j+1];
        float4 vA = Ab[(size_t)sA*32 + lane];
        float4 vB = Ab[(size_t)sB2*32 + lane];
        acc.x = fmaf(nA, vA.x, acc.x); acc.y = fmaf(nA, vA.y, acc.y);
        acc.z = fmaf(nA, vA.z, acc.z); acc.w = fmaf(nA, vA.w, acc.w);
        acc.x = fmaf(nB, vB.x, acc.x); acc.y = fmaf(nB, vB.y, acc.y);
        acc.z = fmaf(nB, vB.z, acc.z); acc.w = fmaf(nB, vB.w, acc.w);
    }
    if (j < e) {
        int sA = g_esrc[j];
        float nA = g_enorm[j];
        float4 vA = Ab[(size_t)sA*32 + lane];
        acc.x = fmaf(nA, vA.x, acc.x); acc.y = fmaf(nA, vA.y, acc.y);
        acc.z = fmaf(nA, vA.z, acc.z); acc.w = fmaf(nA, vA.w, acc.w);
    }
    ((float4*)(H + ((size_t)b*NN + n)*FD))[lane] = acc;
}

// ---------------- per-feature sum/sumsq of relu(H), float4 loads ----------------
__global__ __launch_bounds__(256) void k_relustats(int statoff) {
    __shared__ float ss[8][256];   // [warp][0:128 sum | 128:256 sumsq]
    const int warp = threadIdx.x >> 5;
    const int lane = threadIdx.x & 31;
    const long rb = (long)blockIdx.x * 64;

    float4 s  = make_float4(0.f, 0.f, 0.f, 0.f);
    float4 s2 = make_float4(0.f, 0.f, 0.f, 0.f);
    #pragma unroll
    for (int i = 0; i < 8; i++) {
        long r = rb + warp + 8*i;
        if (r < MR) {
            float4 v = *(const float4*)(g_bufH + r*FD + lane*4);
            v.x = fmaxf(v.x, 0.f); v.y = fmaxf(v.y, 0.f);
            v.z = fmaxf(v.z, 0.f); v.w = fmaxf(v.w, 0.f);
            s.x += v.x; s.y += v.y; s.z += v.z; s.w += v.w;
            s2.x += v.x*v.x; s2.y += v.y*v.y; s2.z += v.z*v.z; s2.w += v.w*v.w;
        }
    }
    *(float4*)&ss[warp][lane*4]       = s;
    *(float4*)&ss[warp][128 + lane*4] = s2;
    __syncthreads();   // uniform work per warp -> no straggler penalty
    int t = threadIdx.x;
    float r = ss[0][t] + ss[1][t] + ss[2][t] + ss[3][t]
            + ss[4][t] + ss[5][t] + ss[6][t] + ss[7][t];
    atomicAdd(&g_stats[statoff + t], r);
}

// ---------------- fold BN1 into W2: W2' = a1⊙W2, cw2 = c1@W2 ----------------
__global__ void k_fin1(const float* __restrict__ W2, const float* __restrict__ g1,
                       const float* __restrict__ be1) {
    __shared__ float a[FD], c[FD];
    int t = threadIdx.x;   // 128
    float inv = 1.0f / (float)MR;
    float mu  = g_stats[t] * inv;
    float var = g_stats[128 + t] * inv - mu*mu;
    float av  = g1[t] * rsqrtf(var + 1e-5f);
    a[t] = av; c[t] = be1[t] - mu*av;
    __syncthreads();
    float acc = 0.f;
    for (int f = 0; f < FD; f++) {
        float w = W2[f*FD + t];
        g_W2p[f*FD + t] = a[f]*w;
        acc = fmaf(c[f], w, acc);
    }
    g_cw2[t] = acc;
}

// ---------------- fold BN2 into Wc: Wc' = a2⊙Wc, bc' = bc + c2@Wc ----------------
__global__ void k_fin2(const float* __restrict__ Wc, const float* __restrict__ bc,
                       const float* __restrict__ g2, const float* __restrict__ be2) {
    __shared__ float a[FD], c[FD];
    int t = threadIdx.x;   // 128
    float inv = 1.0f / (float)MR;
    float mu  = g_stats[256 + t] * inv;
    float var = g_stats[384 + t] * inv - mu*mu;
    float av  = g2[t] * rsqrtf(var + 1e-5f);
    a[t] = av; c[t] = be2[t] - mu*av;
    __syncthreads();
    if (t < NOUT) {
        float acc = bc[t];
        for (int f = 0; f < FD; f++) {
            float w = Wc[f*NOUT + t];
            g_Wcp[f*NOUT + t] = a[f]*w;
            acc = fmaf(c[f], w, acc);
        }
        g_bcp[t] = acc;
    }
}

// ---------------- output head: out = relu(H) @ Wc' + bc', float4 loads ----------------
__global__ void k_out(float* __restrict__ out) {
    __shared__ float Ws[FD*NOUT];
    __shared__ float Hs[8][FD];
    int t = threadIdx.x;   // 128
    #pragma unroll
    for (int i = 0; i < 4; i++)
        *(float4*)&Ws[(t + 128*i)*4] = *(const float4*)&g_Wcp[(t + 128*i)*4];
    long rb = (long)blockIdx.x * 8;
    #pragma unroll
    for (int j = 0; j < 2; j++) {
        int idx = t + 128*j;
        int row = idx >> 5, l = idx & 31;
        long r = rb + row;
        float4 v = make_float4(0.f, 0.f, 0.f, 0.f);
        if (r < MR) {
            v = *(const float4*)(g_bufH + r*FD + l*4);
            v.x = fmaxf(v.x, 0.f); v.y = fmaxf(v.y, 0.f);
            v.z = fmaxf(v.z, 0.f); v.w = fmaxf(v.w, 0.f);
        }
        *(float4*)&Hs[row][l*4] = v;
    }
    __syncthreads();
    int rl = t >> 4, c = t & 15;
    float acc = g_bcp[c];
    #pragma unroll 8
    for (int f = 0; f < FD; f++) acc = fmaf(Hs[rl][f], Ws[f*NOUT + c], acc);
    long r = rb + rl;
    if (r < MR) out[r*NOUT + c] = acc;
}

// ---------------- launcher ----------------
extern "C" void kernel_launch(void* const* d_in, const int* in_sizes, int n_in,
                              void* d_out, int out_size) {
    const float* x   = (const float*)d_in[0];
    const int*   ei  = (const int*)  d_in[1];
    const float* ewp = (const float*)d_in[2];
    const float* W1  = (const float*)d_in[3];
    const float* b1  = (const float*)d_in[4];
    const float* W2  = (const float*)d_in[5];
    const float* b2  = (const float*)d_in[6];
    const float* g1  = (const float*)d_in[7];
    const float* be1 = (const float*)d_in[8];
    const float* g2  = (const float*)d_in[9];
    const float* be2 = (const float*)d_in[10];
    const float* Wc  = (const float*)d_in[11];
    const float* bc  = (const float*)d_in[12];
    float* out = (float*)d_out;

    float *bufA, *bufH, *W2p, *cw2;
    cudaGetSymbolAddress((void**)&bufA, g_bufA);
    cudaGetSymbolAddress((void**)&bufH, g_bufH);
    cudaGetSymbolAddress((void**)&W2p,  g_W2p);
    cudaGetSymbolAddress((void**)&cw2,  g_cw2);

    const int gemmBlocks = (MR + 127) / 128;          // 782
    const dim3 aggGrid((NN + 7) / 8, NB);             // 6250 x 2

    // fork a side stream so layer-1 GEMM overlaps the prep chain
    cudaStream_t s2;
    cudaStreamCreateWithFlags(&s2, cudaStreamNonBlocking);
    cudaEvent_t evFork, evJoin;
    cudaEventCreateWithFlags(&evFork, cudaEventDisableTiming);
    cudaEventCreateWithFlags(&evJoin, cudaEventDisableTiming);

    cudaEventRecord(evFork, 0);
    cudaStreamWaitEvent(s2, evFork, 0);

    // branch A (s2): layer-1 GEMM (depends only on x, W1)
    k_gemm<<<gemmBlocks, 256, 0, s2>>>(x, W1, bufA, nullptr, 0);

    // branch B (main): prep + CSR build
    k_init<<<(NN + 255)/256, 256>>>();
    k_deghist<<<(NE + 255)/256, 256>>>(ei, ewp);
    k_scan1<<<SB, 1024>>>();
    k_scan2<<<1, 64>>>();
    k_scan3<<<SB, 1024>>>();      // also computes dinv
    k_fill<<<(NE + 255)/256, 256>>>(ei, ewp);

    // join: agg needs both bufA (branch A) and CSR (branch B)
    cudaEventRecord(evJoin, s2);
    cudaStreamWaitEvent(0, evJoin, 0);

    // Layer 1
    k_agg<<<aggGrid, 256>>>(bufA, bufH, b1);
    k_relustats<<<(MR + 63)/64, 256>>>(0);
    k_fin1<<<1, 128>>>(W2, g1, be1);

    // Layer 2 (ReLU in GEMM A-load; BN1 folded into W2p/cw2)
    k_gemm<<<gemmBlocks, 256>>>(bufH, W2p, bufA, cw2, 1);
    k_agg<<<aggGrid, 256>>>(bufA, bufH, b2);
    k_relustats<<<(MR + 63)/64, 256>>>(256);
    k_fin2<<<1, 128>>>(Wc, bc, g2, be2);

    // Head (ReLU in load; BN2 folded into Wcp/bcp)
    k_out<<<(MR + 7)/8, 128>>>(out);

    cudaEventDestroy(evFork);
    cudaEventDestroy(evJoin);
    cudaStreamDestroy(s2);
}